// round 10
// baseline (speedup 1.0000x reference)
#include <cuda_runtime.h>
#include <math.h>

#define S_MAX   360
#define S_PAD   384                // padded table size (pads are zero quats)
#define EPS_CLP 1e-6f
#define FULL    0xFFFFFFFFu
#define SPW     16                 // samples per warp (lanes 0..15 own one)
#define NWARP   8                  // warps per block
#define SPB     (SPW * NWARP)      // 128 samples per block

// dot(u, qua_mul(y, q)) == v . q  with v = M(y)^T u (M orthogonal).
// argmin over concat([acos(d), acos(-d)]): track max d (half0) and min d
// (half1) separately; per-lane strict compares keep the lowest index; redux
// min-index among lanes at the max; half0 beats half1 on equal value.
// Zero-pad entries give d == 0 and can never be the final winner: if pads top
// half0 (all real d < 0) then half1 is strictly positive and wins, and vice
// versa.

__device__ __forceinline__ void compute_v(const float4 xv, const float4 yv,
                                          float& vx, float& vy, float& vz, float& vw)
{
    const float inv = rsqrtf(xv.x*xv.x + xv.y*xv.y + xv.z*xv.z + xv.w*xv.w);
    const float ux = xv.x*inv, uy = xv.y*inv, uz = xv.z*inv, uw = xv.w*inv;
    const float px = yv.x, py = yv.y, pz = yv.z, pw = yv.w;
    vx =  ux*pw - uy*pz + uz*py - uw*px;
    vy =  ux*pz + uy*pw - uz*px - uw*py;
    vz = -ux*py + uy*px + uz*pw - uw*pz;
    vw =  ux*px + uy*py + uz*pz + uw*pw;
}

__device__ __forceinline__ void write_result(float* __restrict__ out, int B, int b,
                                             const float4 xv, const float4 yv,
                                             const float4 q, float vbest, bool half0)
{
    const float loss = acosf(vbest);
    const float px = yv.x, py = yv.y, pz = yv.z, pw = yv.w;
    const float qx = q.x,  qy = q.y,  qz = q.z,  qw = q.w;
    const float rw = qw*pw - qx*px - qy*py - qz*pz;
    const float rx = qw*px + qx*pw + qy*pz - qz*py;
    const float ry = qw*py - qx*pz + qy*pw + qz*px;
    const float rz = qw*pz + qx*py - qy*px + qz*pw;
    const float sgn = half0 ? 1.0f : -1.0f;
    out[b] = loss;
    reinterpret_cast<float4*>(out + B)[b]   = make_float4(xv.x*sgn, xv.y*sgn, xv.z*sgn, xv.w*sgn);
    reinterpret_cast<float4*>(out + 5*B)[b] = make_float4(rx, ry, rz, rw);
}

// monotone float<->int key (total order matching float compare; no NaNs here)
__device__ __forceinline__ int   f2ord(float f) { int b = __float_as_int(f); return b ^ ((b >> 31) & 0x7fffffff); }
__device__ __forceinline__ float ord2f(int k)   { return __int_as_float(k ^ ((k >> 31) & 0x7fffffff)); }

__global__ __launch_bounds__(256, 5)   // target 48 regs -> 40 warps/SM
void quer_loss_kernel(const float*  __restrict__ x,
                      const float*  __restrict__ y,
                      const int*    __restrict__ n,
                      const float4* __restrict__ sym,   // [5*360] float4
                      float* __restrict__ out, int B)
{
    __shared__ float4 s4[S_PAD];     // class-4 table, zero-padded (6.1 KB)
    __shared__ float4 ss[4 * 12];    // classes 0..3, 12 entries each
    __shared__ int    qb [SPB];      // queued sample index
    __shared__ float4 qx4[SPB];      // queued xv
    __shared__ float4 qy4[SPB];      // queued yv
    __shared__ float4 qv4[SPB];      // queued v
    __shared__ int    cnt;

    const int tid  = threadIdx.x;
    const int lane = tid & 31;
    const int warp = tid >> 5;

    if (tid == 0) cnt = 0;
    for (int i = tid; i < S_PAD; i += 256)
        s4[i] = (i < S_MAX) ? __ldg(sym + 4 * S_MAX + i) : make_float4(0.f, 0.f, 0.f, 0.f);
    if (tid < 48)
        ss[tid] = __ldg(sym + (tid / 12) * S_MAX + (tid % 12));
    __syncthreads();

    const int base = blockIdx.x * SPB + warp * SPW;
    const int o = lane & 15;         // owned-sample slot within warp
    const int g = lane >> 4;         // group 0/1 handles entries 6g..6g+5
    const int b = base + o;
    const bool valid = (b < B);
    const int bl = valid ? b : (B - 1);

    const float4 xv = __ldg(reinterpret_cast<const float4*>(x) + bl);
    const float4 yv = __ldg(reinterpret_cast<const float4*>(y) + bl);
    const int cls   = __ldg(n + bl);

    float vx, vy, vz, vw;
    compute_v(xv, yv, vx, vy, vz, vw);

    // enqueue class-4 samples with precomputed operands
    if (valid && lane < SPW && cls == 4) {
        const int p = atomicAdd(&cnt, 1);
        qb [p] = b;
        qx4[p] = xv;
        qy4[p] = yv;
        qv4[p] = make_float4(vx, vy, vz, vw);
    }

    // ---- small-class phase: 2 lanes per sample, 6 entries per lane ----
    {
        float best0 = -2.0f, best1 = -2.0f;
        int   i0 = 0, i1 = 0;
        if (cls != 4) {
            const int c = (cls == 0) ? 1 : (cls == 1) ? 2 : (cls == 2) ? 4 : 12;
            #pragma unroll
            for (int k = 0; k < 6; ++k) {
                const int s = g * 6 + k;
                if (s < c) {
                    const float4 q = ss[cls * 12 + s];
                    float d = vx*q.x + vy*q.y + vz*q.z + vw*q.w;
                    d = fminf(fmaxf(d, -1.0f + EPS_CLP), 1.0f - EPS_CLP);
                    if ( d > best0) { best0 =  d; i0 = s; }   // strict > keeps lowest s
                    if (-d > best1) { best1 = -d; i1 = s; }
                }
            }
        }
        // combine the two group-lanes of each sample (xor 16)
        {
            const float t0 = __shfl_xor_sync(FULL, best0, 16);
            const int   k0 = __shfl_xor_sync(FULL, i0,    16);
            if (t0 > best0 || (t0 == best0 && k0 < i0)) { best0 = t0; i0 = k0; }
            const float t1 = __shfl_xor_sync(FULL, best1, 16);
            const int   k1 = __shfl_xor_sync(FULL, i1,    16);
            if (t1 > best1 || (t1 == best1 && k1 < i1)) { best1 = t1; i1 = k1; }
        }
        if (valid && lane < SPW && cls != 4) {
            const bool  half0 = (best0 >= best1);
            const float vbest = half0 ? best0 : best1;
            const int   sbest = half0 ? i0 : i1;
            write_result(out, B, b, xv, yv, ss[cls * 12 + sbest], vbest, half0);
        }
    }

    __syncthreads();                 // queue ready
    const int c4 = cnt;

    // ---- cooperative phase: warps pull balanced work from the queue ----
    for (int i = warp; i < c4; i += NWARP) {
        const float4 vv = qv4[i];    // uniform smem broadcasts

        // single pass: track max d (half0) and min d (half1) with lowest k
        float dmax = -2.0f, dmin = 2.0f;
        int   k0 = 0, k1 = 0;
        #pragma unroll
        for (int k = 0; k < 12; ++k) {
            const float4 q = s4[lane + k * 32];          // pads -> d = 0
            const float d = vv.x*q.x + vv.y*q.y + vv.z*q.z + vv.w*q.w;
            if (d > dmax) { dmax = d; k0 = k; }          // strict: keeps lowest k
            if (d < dmin) { dmin = d; k1 = k; }
        }
        const float best1 = -dmin;

        // cross-lane: max value, then min s among lanes at the max
        const int K0 = f2ord(dmax);
        const int M0 = __reduce_max_sync(FULL, K0);
        const int s0 = __reduce_min_sync(FULL, (K0 == M0) ? (lane + k0 * 32) : 0x7fffffff);
        const int K1 = f2ord(best1);
        const int M1 = __reduce_max_sync(FULL, K1);
        const int s1 = __reduce_min_sync(FULL, (K1 == M1) ? (lane + k1 * 32) : 0x7fffffff);

        if (lane == 0) {
            const float v0 = ord2f(M0), v1 = ord2f(M1);
            const bool  half0 = (v0 >= v1);              // half0 wins ties
            const int   sbest = half0 ? s0 : s1;
            const float vbest = fminf(half0 ? v0 : v1, 1.0f - EPS_CLP);
            write_result(out, B, qb[i], qx4[i], qy4[i], s4[sbest], vbest, half0);
        }
    }
}

extern "C" void kernel_launch(void* const* d_in, const int* in_sizes, int n_in,
                              void* d_out, int out_size)
{
    // metadata order: x[B,4], y[B,4], pred_n[B,5] (unused), n[B],
    //                 sym_qua[5,360,4], sym_mask[5,360] (unused)
    const float*  x   = (const float*) d_in[0];
    const float*  y   = (const float*) d_in[1];
    const int*    n   = (const int*)   d_in[3];
    const float4* sym = (const float4*)d_in[4];
    float* out = (float*)d_out;

    const int B = in_sizes[3];                    // 65536
    const int blocks = (B + SPB - 1) / SPB;       // 512
    quer_loss_kernel<<<blocks, 256>>>(x, y, n, sym, out, B);
}

// round 11
// speedup vs baseline: 1.4775x; 1.4775x over previous
#include <cuda_runtime.h>
#include <math.h>

#define S_MAX   360
#define S_PAD   384                // zero-padded class-4 table
#define EPS_CLP 1e-6f
#define FULL    0xFFFFFFFFu
#define SPW     16                 // samples per warp (lanes 0..15 own one)
#define NWARP   8                  // warps per block
#define SPB     (SPW * NWARP)      // 128 samples per block

// dot(u, qua_mul(y, q)) == v . q  with v = M(y)^T u (M orthogonal).
// argmin over concat([acos(d), acos(-d)]) == max over packed keys
//   key = (|d|_bits & ~0x1F) | (d>=0)<<4 | (15-k)
// giving priority: larger |d|  ->  half0 before half1  ->  lower k (lower s)
// -> lower lane (via ballot/ffs). 5 truncated mantissa bits only affect
// tie-breaks among dots equal to within 2^-18 relative (harmless at 1e-3).
// Zero-pad entries give d = +0 -> key ~ 0, never competitive with real dots.

__device__ __forceinline__ void compute_v(const float4 xv, const float4 yv,
                                          float& vx, float& vy, float& vz, float& vw)
{
    const float inv = rsqrtf(xv.x*xv.x + xv.y*xv.y + xv.z*xv.z + xv.w*xv.w);
    const float ux = xv.x*inv, uy = xv.y*inv, uz = xv.z*inv, uw = xv.w*inv;
    const float px = yv.x, py = yv.y, pz = yv.z, pw = yv.w;
    vx =  ux*pw - uy*pz + uz*py - uw*px;
    vy =  ux*pz + uy*pw - uz*px - uw*py;
    vz = -ux*py + uy*px + uz*pw - uw*pz;
    vw =  ux*px + uy*py + uz*pz + uw*pw;
}

__device__ __forceinline__ void write_result(float* __restrict__ out, int B, int b,
                                             const float4 xv, const float4 yv,
                                             const float4 q, float vbest, bool half0)
{
    const float loss = acosf(vbest);
    const float px = yv.x, py = yv.y, pz = yv.z, pw = yv.w;
    const float qx = q.x,  qy = q.y,  qz = q.z,  qw = q.w;
    const float rw = qw*pw - qx*px - qy*py - qz*pz;
    const float rx = qw*px + qx*pw + qy*pz - qz*py;
    const float ry = qw*py - qx*pz + qy*pw + qz*px;
    const float rz = qw*pz + qx*py - qy*px + qz*pw;
    const float sgn = half0 ? 1.0f : -1.0f;
    out[b] = loss;
    reinterpret_cast<float4*>(out + B)[b]   = make_float4(xv.x*sgn, xv.y*sgn, xv.z*sgn, xv.w*sgn);
    reinterpret_cast<float4*>(out + 5*B)[b] = make_float4(rx, ry, rz, rw);
}

__global__ __launch_bounds__(256, 4)
void quer_loss_kernel(const float*  __restrict__ x,
                      const float*  __restrict__ y,
                      const int*    __restrict__ n,
                      const float4* __restrict__ sym,   // [5*360] float4
                      float* __restrict__ out, int B)
{
    __shared__ float4 s4[S_PAD];     // class-4 table, zero-padded (6.1 KB)
    __shared__ float4 ss[4 * 12];    // classes 0..3, 12 entries each
    __shared__ int    qb [SPB];      // queued sample index
    __shared__ float4 qx4[SPB];      // queued xv
    __shared__ float4 qy4[SPB];      // queued yv
    __shared__ float4 qv4[SPB];      // queued v
    __shared__ int    cnt;

    const int tid  = threadIdx.x;
    const int lane = tid & 31;
    const int warp = tid >> 5;

    if (tid == 0) cnt = 0;
    for (int i = tid; i < S_PAD; i += 256)
        s4[i] = (i < S_MAX) ? __ldg(sym + 4 * S_MAX + i) : make_float4(0.f, 0.f, 0.f, 0.f);
    if (tid < 48)
        ss[tid] = __ldg(sym + (tid / 12) * S_MAX + (tid % 12));
    __syncthreads();

    const int base = blockIdx.x * SPB + warp * SPW;
    const int o = lane & 15;         // owned-sample slot within warp
    const int g = lane >> 4;         // group 0/1 handles entries 6g..6g+5
    const int b = base + o;
    const bool valid = (b < B);
    const int bl = valid ? b : (B - 1);

    const float4 xv = __ldg(reinterpret_cast<const float4*>(x) + bl);
    const float4 yv = __ldg(reinterpret_cast<const float4*>(y) + bl);
    const int cls   = __ldg(n + bl);

    float vx, vy, vz, vw;
    compute_v(xv, yv, vx, vy, vz, vw);

    // enqueue class-4 samples with precomputed operands
    if (valid && lane < SPW && cls == 4) {
        const int p = atomicAdd(&cnt, 1);
        qb [p] = b;
        qx4[p] = xv;
        qy4[p] = yv;
        qv4[p] = make_float4(vx, vy, vz, vw);
    }

    // ---- small-class phase: 2 lanes per sample, 6 entries per lane ----
    {
        float best0 = -2.0f, best1 = -2.0f;
        int   i0 = 0, i1 = 0;
        if (cls != 4) {
            const int c = (cls == 0) ? 1 : (cls == 1) ? 2 : (cls == 2) ? 4 : 12;
            #pragma unroll
            for (int k = 0; k < 6; ++k) {
                const int s = g * 6 + k;
                if (s < c) {
                    const float4 q = ss[cls * 12 + s];
                    float d = vx*q.x + vy*q.y + vz*q.z + vw*q.w;
                    d = fminf(fmaxf(d, -1.0f + EPS_CLP), 1.0f - EPS_CLP);
                    if ( d > best0) { best0 =  d; i0 = s; }   // strict > keeps lowest s
                    if (-d > best1) { best1 = -d; i1 = s; }
                }
            }
        }
        // combine the two group-lanes of each sample (xor 16)
        {
            const float t0 = __shfl_xor_sync(FULL, best0, 16);
            const int   k0 = __shfl_xor_sync(FULL, i0,    16);
            if (t0 > best0 || (t0 == best0 && k0 < i0)) { best0 = t0; i0 = k0; }
            const float t1 = __shfl_xor_sync(FULL, best1, 16);
            const int   k1 = __shfl_xor_sync(FULL, i1,    16);
            if (t1 > best1 || (t1 == best1 && k1 < i1)) { best1 = t1; i1 = k1; }
        }
        if (valid && lane < SPW && cls != 4) {
            const bool  half0 = (best0 >= best1);
            const float vbest = half0 ? best0 : best1;
            const int   sbest = half0 ? i0 : i1;
            write_result(out, B, b, xv, yv, ss[cls * 12 + sbest], vbest, half0);
        }
    }

    __syncthreads();                 // queue ready
    const int c4 = cnt;

    // ---- cooperative phase: warps pull balanced work from the queue ----
    for (int i = warp; i < c4; i += NWARP) {
        const float4 vv = qv4[i];    // uniform smem broadcasts

        // packed-key max over 12 elements; two alternating IMNMX chains
        int kA = 0, kB = 0;
        #pragma unroll
        for (int k = 0; k < 12; ++k) {
            const float4 q = s4[lane + k * 32];          // pads -> d = +0
            const float d = vv.x*q.x + vv.y*q.y + vv.z*q.z + vv.w*q.w;
            const int db  = __float_as_int(d);
            const int key = (db & 0x7FFFFFE0)            // |d| truncated
                          | ((((~db) >> 31) & 1) << 4)   // half0 flag (d>=0)
                          | (15 - k);                    // lower k preferred
            if (k & 1) kB = max(kB, key); else kA = max(kA, key);
        }
        const int mykey = max(kA, kB);

        const int M = __reduce_max_sync(FULL, mykey);
        const unsigned who = __ballot_sync(FULL, mykey == M);

        if (lane == (int)(__ffs(who) - 1)) {             // lowest lane at max
            const int  kk    = 15 - (M & 15);
            const bool half0 = (M >> 4) & 1;
            const int  sbest = lane + kk * 32;
            const float4 q = s4[sbest];
            const float d = vv.x*q.x + vv.y*q.y + vv.z*q.z + vv.w*q.w;  // exact
            const float vbest = fminf(fabsf(d), 1.0f - EPS_CLP);
            write_result(out, B, qb[i], qx4[i], qy4[i], q, vbest, half0);
        }
    }
}

extern "C" void kernel_launch(void* const* d_in, const int* in_sizes, int n_in,
                              void* d_out, int out_size)
{
    // metadata order: x[B,4], y[B,4], pred_n[B,5] (unused), n[B],
    //                 sym_qua[5,360,4], sym_mask[5,360] (unused)
    const float*  x   = (const float*) d_in[0];
    const float*  y   = (const float*) d_in[1];
    const int*    n   = (const int*)   d_in[3];
    const float4* sym = (const float4*)d_in[4];
    float* out = (float*)d_out;

    const int B = in_sizes[3];                    // 65536
    const int blocks = (B + SPB - 1) / SPB;       // 512
    quer_loss_kernel<<<blocks, 256>>>(x, y, n, sym, out, B);
}

// round 12
// speedup vs baseline: 1.4812x; 1.0025x over previous
#include <cuda_runtime.h>
#include <math.h>

#define S_MAX   360
#define S_PAD   384                // zero-padded class-4 table
#define EPS_CLP 1e-6f
#define FULL    0xFFFFFFFFu
#define SPW     14                 // samples per warp (lanes 0..13 own one)
#define NWARP   8                  // warps per block
#define SPB     (SPW * NWARP)      // 112 samples per block
#define NSM     148                // GB300 SM count (grid rounded to 4/SM)

// dot(u, qua_mul(y, q)) == v . q  with v = M(y)^T u (M orthogonal).
// argmin over concat([acos(d), acos(-d)]) == max over packed keys
//   key = (|d|_bits & ~0x1F) | (d>=0)<<4 | (15-k)
// priority: larger |d| -> half0 before half1 -> lower k (lower s) -> lower
// lane (ballot/ffs). 5 truncated mantissa bits only affect tie-breaks among
// dots equal to within 2^-18 relative. Zero-pad entries give d = +0 -> key
// ~0, never competitive with real dots.

__device__ __forceinline__ void compute_v(const float4 xv, const float4 yv,
                                          float& vx, float& vy, float& vz, float& vw)
{
    const float inv = rsqrtf(xv.x*xv.x + xv.y*xv.y + xv.z*xv.z + xv.w*xv.w);
    const float ux = xv.x*inv, uy = xv.y*inv, uz = xv.z*inv, uw = xv.w*inv;
    const float px = yv.x, py = yv.y, pz = yv.z, pw = yv.w;
    vx =  ux*pw - uy*pz + uz*py - uw*px;
    vy =  ux*pz + uy*pw - uz*px - uw*py;
    vz = -ux*py + uy*px + uz*pw - uw*pz;
    vw =  ux*px + uy*py + uz*pz + uw*pw;
}

__device__ __forceinline__ void write_result(float* __restrict__ out, int B, int b,
                                             const float4 xv, const float4 yv,
                                             const float4 q, float vbest, bool half0)
{
    const float loss = acosf(vbest);
    const float px = yv.x, py = yv.y, pz = yv.z, pw = yv.w;
    const float qx = q.x,  qy = q.y,  qz = q.z,  qw = q.w;
    const float rw = qw*pw - qx*px - qy*py - qz*pz;
    const float rx = qw*px + qx*pw + qy*pz - qz*py;
    const float ry = qw*py - qx*pz + qy*pw + qz*px;
    const float rz = qw*pz + qx*py - qy*px + qz*pw;
    const float sgn = half0 ? 1.0f : -1.0f;
    out[b] = loss;
    reinterpret_cast<float4*>(out + B)[b]   = make_float4(xv.x*sgn, xv.y*sgn, xv.z*sgn, xv.w*sgn);
    reinterpret_cast<float4*>(out + 5*B)[b] = make_float4(rx, ry, rz, rw);
}

__global__ __launch_bounds__(256, 4)
void quer_loss_kernel(const float*  __restrict__ x,
                      const float*  __restrict__ y,
                      const int*    __restrict__ n,
                      const float4* __restrict__ sym,   // [5*360] float4
                      float* __restrict__ out, int B)
{
    __shared__ float4 s4[S_PAD];     // class-4 table, zero-padded (6.1 KB)
    __shared__ float4 ss[4 * 12];    // classes 0..3, 12 entries each
    __shared__ int    qb [SPB];      // queued sample index
    __shared__ float4 qx4[SPB];      // queued xv
    __shared__ float4 qy4[SPB];      // queued yv
    __shared__ float4 qv4[SPB];      // queued v
    __shared__ int    cnt;

    const int tid  = threadIdx.x;
    const int lane = tid & 31;
    const int warp = tid >> 5;

    if (tid == 0) cnt = 0;
    for (int i = tid; i < S_PAD; i += 256)
        s4[i] = (i < S_MAX) ? __ldg(sym + 4 * S_MAX + i) : make_float4(0.f, 0.f, 0.f, 0.f);
    if (tid < 48)
        ss[tid] = __ldg(sym + (tid / 12) * S_MAX + (tid % 12));
    __syncthreads();

    const int base = blockIdx.x * SPB + warp * SPW;
    const int o = lane & 15;         // owned-sample slot within warp (0..13 used)
    const int g = lane >> 4;         // group 0/1 handles entries 6g..6g+5
    const int b = base + o;
    const bool valid = (o < SPW) && (b < B);
    const int bl = valid ? b : (B - 1);

    const float4 xv = __ldg(reinterpret_cast<const float4*>(x) + bl);
    const float4 yv = __ldg(reinterpret_cast<const float4*>(y) + bl);
    const int cls   = __ldg(n + bl);

    float vx, vy, vz, vw;
    compute_v(xv, yv, vx, vy, vz, vw);

    // enqueue class-4 samples with precomputed operands
    if (valid && lane < 16 && cls == 4) {
        const int p = atomicAdd(&cnt, 1);
        qb [p] = b;
        qx4[p] = xv;
        qy4[p] = yv;
        qv4[p] = make_float4(vx, vy, vz, vw);
    }

    // ---- small-class phase: 2 lanes per sample, 6 entries per lane ----
    {
        float best0 = -2.0f, best1 = -2.0f;
        int   i0 = 0, i1 = 0;
        if (valid && cls != 4) {
            const int c = (cls == 0) ? 1 : (cls == 1) ? 2 : (cls == 2) ? 4 : 12;
            #pragma unroll
            for (int k = 0; k < 6; ++k) {
                const int s = g * 6 + k;
                if (s < c) {
                    const float4 q = ss[cls * 12 + s];
                    float d = vx*q.x + vy*q.y + vz*q.z + vw*q.w;
                    d = fminf(fmaxf(d, -1.0f + EPS_CLP), 1.0f - EPS_CLP);
                    if ( d > best0) { best0 =  d; i0 = s; }   // strict > keeps lowest s
                    if (-d > best1) { best1 = -d; i1 = s; }
                }
            }
        }
        // combine the two group-lanes of each sample (xor 16)
        {
            const float t0 = __shfl_xor_sync(FULL, best0, 16);
            const int   k0 = __shfl_xor_sync(FULL, i0,    16);
            if (t0 > best0 || (t0 == best0 && k0 < i0)) { best0 = t0; i0 = k0; }
            const float t1 = __shfl_xor_sync(FULL, best1, 16);
            const int   k1 = __shfl_xor_sync(FULL, i1,    16);
            if (t1 > best1 || (t1 == best1 && k1 < i1)) { best1 = t1; i1 = k1; }
        }
        if (valid && lane < 16 && cls != 4) {
            const bool  half0 = (best0 >= best1);
            const float vbest = half0 ? best0 : best1;
            const int   sbest = half0 ? i0 : i1;
            write_result(out, B, b, xv, yv, ss[cls * 12 + sbest], vbest, half0);
        }
    }

    __syncthreads();                 // queue ready
    const int c4 = cnt;

    // ---- cooperative phase: warps pull balanced work from the queue ----
    for (int i = warp; i < c4; i += NWARP) {
        const float4 vv = qv4[i];    // uniform smem broadcasts

        // packed-key max over 12 elements; two alternating IMNMX chains
        int kA = 0, kB = 0;
        #pragma unroll
        for (int k = 0; k < 12; ++k) {
            const float4 q = s4[lane + k * 32];          // pads -> d = +0
            const float d = vv.x*q.x + vv.y*q.y + vv.z*q.z + vv.w*q.w;
            const int db  = __float_as_int(d);
            const int key = (db & 0x7FFFFFE0)            // |d| truncated
                          | ((((~db) >> 31) & 1) << 4)   // half0 flag (d>=0)
                          | (15 - k);                    // lower k preferred
            if (k & 1) kB = max(kB, key); else kA = max(kA, key);
        }
        const int mykey = max(kA, kB);

        const int M = __reduce_max_sync(FULL, mykey);
        const unsigned who = __ballot_sync(FULL, mykey == M);

        if (lane == (int)(__ffs(who) - 1)) {             // lowest lane at max
            const int  kk    = 15 - (M & 15);
            const bool half0 = (M >> 4) & 1;
            const int  sbest = lane + kk * 32;
            const float4 q = s4[sbest];
            const float d = vv.x*q.x + vv.y*q.y + vv.z*q.z + vv.w*q.w;  // exact
            const float vbest = fminf(fabsf(d), 1.0f - EPS_CLP);
            write_result(out, B, qb[i], qx4[i], qy4[i], q, vbest, half0);
        }
    }
}

extern "C" void kernel_launch(void* const* d_in, const int* in_sizes, int n_in,
                              void* d_out, int out_size)
{
    // metadata order: x[B,4], y[B,4], pred_n[B,5] (unused), n[B],
    //                 sym_qua[5,360,4], sym_mask[5,360] (unused)
    const float*  x   = (const float*) d_in[0];
    const float*  y   = (const float*) d_in[1];
    const int*    n   = (const int*)   d_in[3];
    const float4* sym = (const float4*)d_in[4];
    float* out = (float*)d_out;

    const int B = in_sizes[3];                    // 65536
    int blocks = (B + SPB - 1) / SPB;             // 586 for B=65536
    blocks = ((blocks + NSM - 1) / NSM) * NSM;    // round to 4 blocks/SM: 592
    quer_loss_kernel<<<blocks, 256>>>(x, y, n, sym, out, B);
}